// round 16
// baseline (speedup 1.0000x reference)
#include <cuda_runtime.h>
#include <math.h>
#include <stdint.h>

#define NC   256
#define HW   16384
#define NP   320
#define TAUF 20.0f
#define EPSF 1e-4f
#define KC   16          // K per staged chunk
#define NCH  (NC / KC)   // 16 chunks
#define QSTR 20          // smem row stride (floats) — 20 => r*20 mod 32 distinct
#define PSTR 20

// Scratch (device globals — no allocation allowed)
__device__ float g_protos[NP * NC];        // pooled protos [p][c]
__device__ float g_pH[NCH * NP * KC];      // proto hi, chunked+pair-permuted
__device__ float g_pL[NCH * NP * KC];      // proto lo (tf32), same layout

__device__ __forceinline__ float tf32_hi(float v) {
    uint32_t u;
    asm("cvt.rna.tf32.f32 %0, %1;" : "=r"(u) : "f"(v));
    return __uint_as_float(u);
}

__device__ __forceinline__ void mma8(float* d, uint32_t a0, uint32_t a1,
                                     uint32_t a2, uint32_t a3,
                                     uint32_t b0, uint32_t b1) {
    asm volatile(
        "mma.sync.aligned.m16n8k8.row.col.f32.tf32.tf32.f32 "
        "{%0,%1,%2,%3}, {%4,%5,%6,%7}, {%8,%9}, {%0,%1,%2,%3};"
        : "+f"(d[0]), "+f"(d[1]), "+f"(d[2]), "+f"(d[3])
        : "r"(a0), "r"(a1), "r"(a2), "r"(a3), "r"(b0), "r"(b1));
}

// pair-permuted position within a 16-float k-chunk row:
// kc -> oct*8 + (kc&3)*2 + ((kc>>2)&1)  (puts k and k+4 adjacent = one LDS.64)
__device__ __forceinline__ int kpos(int kc) {
    return ((kc >> 3) << 3) + ((kc & 3) << 1) + ((kc >> 2) & 1);
}

// ---------------------------------------------------------------------------
// Kernel A: 16x16 average pool (R14 version — measured at HBM ceiling)
// ---------------------------------------------------------------------------
__global__ __launch_bounds__(256) void pool_kernel(const float* __restrict__ sup)
{
    __shared__ float sm[8][256];
    int c = blockIdx.x, s = blockIdx.y;
    const float4* plane = (const float4*)(sup + (size_t)(s * NC + c) * HW);
    int t = threadIdx.x;

    float4 p[8];
#pragma unroll
    for (int g = 0; g < 8; g++) p[g] = make_float4(0.f, 0.f, 0.f, 0.f);
#pragma unroll
    for (int i = 0; i < 16; i++) {
        float4 v = plane[t + 256 * i];
        int g = i >> 1;
        p[g].x += v.x; p[g].y += v.y; p[g].z += v.z; p[g].w += v.w;
    }
#pragma unroll
    for (int g = 0; g < 8; g++)
        sm[g][t] = (p[g].x + p[g].y) + (p[g].z + p[g].w);
    __syncthreads();

    if (t < 64) {
        int gy = t >> 3, gx = t & 7;
        float acc = 0.f;
#pragma unroll
        for (int w = 0; w < 8; w++)
#pragma unroll
            for (int l4 = 0; l4 < 4; l4++)
                acc += sm[gy][w * 32 + gx * 4 + l4];
        g_protos[(s * 64 + gy * 8 + gx) * NC + c] = acc * (1.0f / 256.0f);
    }
}

// ---------------------------------------------------------------------------
// Kernel B: center + L2-normalize protos; emit tf32 hi/lo in the chunked,
// pair-permuted layout g_pH[chunk][p][16].
// grid 320, block 256
// ---------------------------------------------------------------------------
__global__ void proto_norm_kernel()
{
    __shared__ float red[8];
    int p = blockIdx.x, c = threadIdx.x;
    float v = g_protos[p * NC + c];

    float t = v;
#pragma unroll
    for (int o = 16; o; o >>= 1) t += __shfl_xor_sync(0xffffffffu, t, o);
    if ((c & 31) == 0) red[c >> 5] = t;
    __syncthreads();
    float tot = 0.f;
#pragma unroll
    for (int i = 0; i < 8; i++) tot += red[i];
    float mean = tot * (1.0f / 256.0f);
    float ctr = v - mean;
    __syncthreads();

    t = ctr * ctr;
#pragma unroll
    for (int o = 16; o; o >>= 1) t += __shfl_xor_sync(0xffffffffu, t, o);
    if ((c & 31) == 0) red[c >> 5] = t;
    __syncthreads();
    tot = 0.f;
#pragma unroll
    for (int i = 0; i < 8; i++) tot += red[i];

    float inv = 1.0f / fmaxf(sqrtf(tot), EPSF);
    float w = ctr * inv;

    float hi = tf32_hi(w);
    float lo = tf32_hi(w - hi);

    int ch = c >> 4, kc = c & 15;
    int idx = (ch * NP + p) * KC + kpos(kc);
    g_pH[idx] = hi;
    g_pL[idx] = lo;
}

// ---------------------------------------------------------------------------
// Kernel D: 4xTF32 warp-MMA GEMM (64 px x 320 protos x 256 ch per CTA) +
// fused qstat + softmax/argmax/weighted-mean epilogue.
// 8 warps: warp = (m-tile = w&3 -> 16 px) x (n-half = w>>2 -> 160 protos).
// mma.sync m16n8k8 tf32, 4 passes (hh, hl, lh, ll) => fp32-class accuracy.
// Smem rows stride 20 floats: r*20 mod 32 distinct for r mod 8 => LDS.64 at
// the 2-phase floor. Protos are zero-mean => raw q works (centering folds
// into the final qinv scale).
// ---------------------------------------------------------------------------
__global__ __launch_bounds__(256, 2) void main_kernel(const float* __restrict__ qry,
                                                      float* __restrict__ out)
{
    extern __shared__ float sm[];
    float* Qh = sm;                 // 64*20
    float* Ql = sm + 1280;          // 64*20
    float* Ph = sm + 2560;          // 320*20
    float* Pl = sm + 8960;          // 320*20  (total 15360 floats = 61440 B)

    int tid = threadIdx.x;
    int m0  = blockIdx.x * 64;
    int w   = tid >> 5, l = tid & 31;
    int g   = l >> 2, tig = l & 3;
    int mt  = (w & 3) * 16;         // local m-tile base
    int nh  = w >> 2;               // proto half (0/1)

    float acc[20][4];
#pragma unroll
    for (int i = 0; i < 20; i++)
#pragma unroll
        for (int j = 0; j < 4; j++) acc[i][j] = 0.f;

    int lm = tid & 63, cq = tid >> 6;
    float s = 0.f, ss = 0.f;

    for (int ch = 0; ch < NCH; ch++) {
        int kb = ch * KC;
        // ---- stage Q (hi/lo split + stats); thread: pixel lm, 4 channels
#pragma unroll
        for (int i = 0; i < 4; i++) {
            int c = cq * 4 + i;
            float v = qry[(size_t)(kb + c) * HW + m0 + lm];
            s += v; ss += v * v;
            float hi = tf32_hi(v);
            float lo = tf32_hi(v - hi);
            int pos = lm * QSTR + kpos(c);
            Qh[pos] = hi;
            Ql[pos] = lo;
        }
        // ---- stage P: 1280 float4 per array (5 per thread)
        {
            const float4* srcH = (const float4*)(g_pH + (size_t)ch * NP * KC);
            const float4* srcL = (const float4*)(g_pL + (size_t)ch * NP * KC);
#pragma unroll
            for (int i = 0; i < 5; i++) {
                int idx = tid + i * 256;
                int p = idx >> 2, q4 = idx & 3;
                *(float4*)&Ph[p * PSTR + q4 * 4] = srcH[idx];
                *(float4*)&Pl[p * PSTR + q4 * 4] = srcL[idx];
            }
        }
        __syncthreads();

        // ---- compute: 2 k8-steps x 20 n-tiles x 4 passes
#pragma unroll
        for (int s8 = 0; s8 < 2; s8++) {
            int r = mt + g;
            float2 h02 = *(float2*)&Qh[r * QSTR + s8 * 8 + tig * 2];
            float2 h13 = *(float2*)&Qh[(r + 8) * QSTR + s8 * 8 + tig * 2];
            float2 l02 = *(float2*)&Ql[r * QSTR + s8 * 8 + tig * 2];
            float2 l13 = *(float2*)&Ql[(r + 8) * QSTR + s8 * 8 + tig * 2];
            uint32_t ah0 = __float_as_uint(h02.x), ah2 = __float_as_uint(h02.y);
            uint32_t ah1 = __float_as_uint(h13.x), ah3 = __float_as_uint(h13.y);
            uint32_t al0 = __float_as_uint(l02.x), al2 = __float_as_uint(l02.y);
            uint32_t al1 = __float_as_uint(l13.x), al3 = __float_as_uint(l13.y);
#pragma unroll
            for (int nt = 0; nt < 20; nt++) {
                int pr = nh * 160 + nt * 8 + g;
                float2 bh = *(float2*)&Ph[pr * PSTR + s8 * 8 + tig * 2];
                float2 bl = *(float2*)&Pl[pr * PSTR + s8 * 8 + tig * 2];
                uint32_t bh0 = __float_as_uint(bh.x), bh1 = __float_as_uint(bh.y);
                uint32_t bl0 = __float_as_uint(bl.x), bl1 = __float_as_uint(bl.y);
                mma8(acc[nt], ah0, ah1, ah2, ah3, bh0, bh1);
                mma8(acc[nt], ah0, ah1, ah2, ah3, bl0, bl1);
                mma8(acc[nt], al0, al1, al2, al3, bh0, bh1);
                mma8(acc[nt], al0, al1, al2, al3, bl0, bl1);
            }
        }
        __syncthreads();
    }

    // ---- epilogue scratch (reuses P area; everyone past final sync) ----
    float2* sstat = (float2*)(sm + 2560);     // [64 px][4] partial (s, ss)
    float*  sqi   = sm + 3072;                // [64]  qinv*TAU
    float*  smaxv = sm + 3136;                // [2][64] raw max
    int*    smaxi = (int*)(sm + 3264);        // [2][64] argmax
    float*  sse   = sm + 3392;                // [2][64]
    float*  ssn   = sm + 3520;                // [2][64]
    int*    sgidx = (int*)(sm + 3648);        // [64]

    sstat[lm * 4 + cq] = make_float2(s, ss);
    __syncthreads();
    if (tid < 64) {
        float S = 0.f, SS = 0.f;
#pragma unroll
        for (int j = 0; j < 4; j++) {
            float2 t = sstat[tid * 4 + j];
            S += t.x; SS += t.y;
        }
        float var = SS - S * S * (1.0f / 256.0f);
        sqi[tid] = TAUF / fmaxf(sqrtf(fmaxf(var, 0.f)), EPSF);
    }
    __syncthreads();

    // per-lane: rows g (acc cols 0,1) and g+8 (acc cols 2,3)
#pragma unroll
    for (int hv = 0; hv < 2; hv++) {
        int lmx = mt + g + hv * 8;
        float vmax = -1e30f; int vidx = 0;
#pragma unroll
        for (int nt = 0; nt < 20; nt++)
#pragma unroll
            for (int cc = 0; cc < 2; cc++) {
                float v = acc[nt][hv * 2 + cc];
                int pidx = nh * 160 + nt * 8 + tig * 2 + cc;
                if (v > vmax) { vmax = v; vidx = pidx; }
            }
#pragma unroll
        for (int o = 1; o <= 2; o <<= 1) {
            float om = __shfl_xor_sync(0xffffffffu, vmax, o, 4);
            int   oi = __shfl_xor_sync(0xffffffffu, vidx, o, 4);
            if (om > vmax || (om == vmax && oi < vidx)) { vmax = om; vidx = oi; }
        }
        if (tig == 0) { smaxv[nh * 64 + lmx] = vmax; smaxi[nh * 64 + lmx] = vidx; }
    }
    __syncthreads();

#pragma unroll
    for (int hv = 0; hv < 2; hv++) {
        int lmx = mt + g + hv * 8;
        float v0 = smaxv[lmx], v1 = smaxv[64 + lmx];
        int   i0 = smaxi[lmx], i1 = smaxi[64 + lmx];
        float gmax; int gidx;
        if (v0 > v1 || (v0 == v1 && i0 < i1)) { gmax = v0; gidx = i0; }
        else                                  { gmax = v1; gidx = i1; }
        float sc = sqi[lmx];
        float se = 0.f, sn = 0.f;
#pragma unroll
        for (int nt = 0; nt < 20; nt++)
#pragma unroll
            for (int cc = 0; cc < 2; cc++) {
                float v = acc[nt][hv * 2 + cc];
                float e = __expf((v - gmax) * sc);
                se += e; sn += e * (v * sc);
            }
#pragma unroll
        for (int o = 1; o <= 2; o <<= 1) {
            se += __shfl_xor_sync(0xffffffffu, se, o, 4);
            sn += __shfl_xor_sync(0xffffffffu, sn, o, 4);
        }
        if (tig == 0) {
            sse[nh * 64 + lmx] = se;
            ssn[nh * 64 + lmx] = sn;
            if (nh == 0) sgidx[lmx] = gidx;
        }
    }
    __syncthreads();

    if (tid < 64) {
        float SE = sse[tid] + sse[64 + tid];
        float SN = ssn[tid] + ssn[64 + tid];
        out[m0 + tid]      = SN / SE;             // pred_grid
        out[HW + m0 + tid] = (float)sgidx[tid];   // debug_assign
    }
}

// ---------------------------------------------------------------------------
#define MAIN_SMEM (15360 * 4)

extern "C" void kernel_launch(void* const* d_in, const int* in_sizes, int n_in,
                              void* d_out, int out_size)
{
    const float* qry = (const float*)d_in[0];   // (1,1,256,128,128)
    const float* sup = (const float*)d_in[1];   // (1,5,1,256,128,128)
    // d_in[2] (sup_y) and d_in[3] (thresh) are dead in the reference.
    float* out = (float*)d_out;                 // [pred_grid | debug_assign]

    cudaFuncSetAttribute(main_kernel, cudaFuncAttributeMaxDynamicSharedMemorySize,
                         MAIN_SMEM);

    pool_kernel<<<dim3(256, 5), 256>>>(sup);
    proto_norm_kernel<<<320, 256>>>();
    main_kernel<<<256, 256, MAIN_SMEM>>>(qry, out);
}

// round 17
// speedup vs baseline: 1.2331x; 1.2331x over previous
#include <cuda_runtime.h>
#include <cuda_bf16.h>
#include <math.h>
#include <stdint.h>

#define NC   256
#define HW   16384
#define NP   320
#define TAUF 20.0f
#define EPSF 1e-4f
#define KC   32            // channels per staged chunk
#define NCH  (NC / KC)     // 8 chunks
#define RSTR 24            // smem row stride in uint32 words (96 B) — r*24%32 ∈ {0,24,16,8}

// Scratch (device globals — no allocation allowed)
__device__ float    g_protos[NP * NC];        // pooled protos [p][c]
__device__ float    g_pn[NP * NC];            // normalized protos fp32 [p][c] (fixup)
__device__ uint32_t g_pbH[NCH * NP * 16];     // proto hi bf16x2, chunked+slot-permuted
__device__ uint32_t g_pbL[NCH * NP * 16];     // proto lo bf16x2
__device__ int2     g_top2[HW];               // per-pixel top-2 candidate indices

// bf16 mma m16n8k16: D rows g,g+8; D cols 2*tig+cc; B col=g (proto row nt*8+g)
__device__ __forceinline__ void mma16(float* d, uint32_t a0, uint32_t a1,
                                      uint32_t a2, uint32_t a3,
                                      uint32_t b0, uint32_t b1) {
    asm volatile(
        "mma.sync.aligned.m16n8k16.row.col.f32.bf16.bf16.f32 "
        "{%0,%1,%2,%3}, {%4,%5,%6,%7}, {%8,%9}, {%0,%1,%2,%3};"
        : "+f"(d[0]), "+f"(d[1]), "+f"(d[2]), "+f"(d[3])
        : "r"(a0), "r"(a1), "r"(a2), "r"(a3), "r"(b0), "r"(b1));
}

// slot permutation within a k16-step: pair p (k=2p,2p+1) -> slot ((p&3)*2)|(p>>2)
// => slots (2t, 2t+1) hold pairs (t, t+4): one LDS.64 per fragment half.
__device__ __forceinline__ int pslot(int p) { return ((p & 3) << 1) | (p >> 2); }

// ---------------------------------------------------------------------------
// Kernel A: 16x16 average pool (R14 version — measured at HBM ceiling)
// ---------------------------------------------------------------------------
__global__ __launch_bounds__(256) void pool_kernel(const float* __restrict__ sup)
{
    __shared__ float sm[8][256];
    int c = blockIdx.x, s = blockIdx.y;
    const float4* plane = (const float4*)(sup + (size_t)(s * NC + c) * HW);
    int t = threadIdx.x;

    float4 p[8];
#pragma unroll
    for (int g = 0; g < 8; g++) p[g] = make_float4(0.f, 0.f, 0.f, 0.f);
#pragma unroll
    for (int i = 0; i < 16; i++) {
        float4 v = plane[t + 256 * i];
        int g = i >> 1;
        p[g].x += v.x; p[g].y += v.y; p[g].z += v.z; p[g].w += v.w;
    }
#pragma unroll
    for (int g = 0; g < 8; g++)
        sm[g][t] = (p[g].x + p[g].y) + (p[g].z + p[g].w);
    __syncthreads();

    if (t < 64) {
        int gy = t >> 3, gx = t & 7;
        float acc = 0.f;
#pragma unroll
        for (int w = 0; w < 8; w++)
#pragma unroll
            for (int l4 = 0; l4 < 4; l4++)
                acc += sm[gy][w * 32 + gx * 4 + l4];
        g_protos[(s * 64 + gy * 8 + gx) * NC + c] = acc * (1.0f / 256.0f);
    }
}

// ---------------------------------------------------------------------------
// Kernel B: center + L2-normalize protos; emit fp32 (fixup) + bf16 hi/lo in
// the chunked slot-permuted packed layout.  grid 320, block 256
// ---------------------------------------------------------------------------
__global__ void proto_norm_kernel()
{
    __shared__ float red[8];
    int p = blockIdx.x, c = threadIdx.x;
    float v = g_protos[p * NC + c];

    float t = v;
#pragma unroll
    for (int o = 16; o; o >>= 1) t += __shfl_xor_sync(0xffffffffu, t, o);
    if ((c & 31) == 0) red[c >> 5] = t;
    __syncthreads();
    float tot = 0.f;
#pragma unroll
    for (int i = 0; i < 8; i++) tot += red[i];
    float mean = tot * (1.0f / 256.0f);
    float ctr = v - mean;
    __syncthreads();

    t = ctr * ctr;
#pragma unroll
    for (int o = 16; o; o >>= 1) t += __shfl_xor_sync(0xffffffffu, t, o);
    if ((c & 31) == 0) red[c >> 5] = t;
    __syncthreads();
    tot = 0.f;
#pragma unroll
    for (int i = 0; i < 8; i++) tot += red[i];

    float inv = 1.0f / fmaxf(sqrtf(tot), EPSF);
    float w = ctr * inv;
    g_pn[p * NC + c] = w;

    __nv_bfloat16 hb = __float2bfloat16(w);
    float hf = __bfloat162float(hb);
    __nv_bfloat16 lb = __float2bfloat16(w - hf);
    uint32_t myHL = (uint32_t)__bfloat16_as_ushort(hb)
                  | ((uint32_t)__bfloat16_as_ushort(lb) << 16);
    uint32_t nbHL = __shfl_down_sync(0xffffffffu, myHL, 1);
    if ((c & 1) == 0) {
        uint32_t hiPair = (myHL & 0xFFFFu) | ((nbHL & 0xFFFFu) << 16);
        uint32_t loPair = (myHL >> 16) | (nbHL & 0xFFFF0000u);
        int ch = c >> 5, kc = c & 31;
        int s8 = kc >> 4, kp = (kc & 15) >> 1;
        int idx = (ch * NP + p) * 16 + s8 * 8 + pslot(kp);
        g_pbH[idx] = hiPair;
        g_pbL[idx] = loPair;
    }
}

// ---------------------------------------------------------------------------
// Kernel D: bf16 3-pass split warp-MMA GEMM (64 px x 320 protos x 256 ch per
// CTA) + fused qstat + softmax/weighted-mean + noisy top-2 extraction.
// 8 warps: (m-tile = w&3 -> 16 px) x (n-half = w>>2 -> 160 protos);
// mma m16n8k16, passes hh+hl+lh (ll dropped; fp32-class after exact fixup).
// Fragments: one LDS.64 each via slot permutation; rows stride 24 words.
// ---------------------------------------------------------------------------
__global__ __launch_bounds__(256, 2) void main_kernel(const float* __restrict__ qry,
                                                      float* __restrict__ out)
{
    extern __shared__ uint32_t smw[];
    uint32_t* Qh = smw;              // 64*24
    uint32_t* Ql = smw + 1536;       // 64*24
    uint32_t* Ph = smw + 3072;       // 320*24
    uint32_t* Pl = smw + 10752;      // 320*24   (18432 words = 72 KB)

    int tid = threadIdx.x;
    int m0  = blockIdx.x * 64;
    int w   = tid >> 5, l = tid & 31;
    int g   = l >> 2, tig = l & 3;
    int mt  = (w & 3) * 16;          // local m-tile base (16 px)
    int nh  = w >> 2;                // proto half (0/1)

    float acc[20][4];
#pragma unroll
    for (int i = 0; i < 20; i++)
#pragma unroll
        for (int j = 0; j < 4; j++) acc[i][j] = 0.f;

    int lm = tid & 63, cq = tid >> 6;   // staging: pixel lm, quarter cq
    float s = 0.f, ss = 0.f;

    for (int ch = 0; ch < NCH; ch++) {
        int kb = ch * KC;
        // ---- stage Q: px lm, 4 channel-pairs (pp = cq*4+i); stats fused ----
#pragma unroll
        for (int i = 0; i < 4; i++) {
            int pp = cq * 4 + i;
            int c0 = kb + pp * 2;
            float v0 = qry[(size_t)c0 * HW + m0 + lm];
            float v1 = qry[(size_t)(c0 + 1) * HW + m0 + lm];
            s += v0 + v1; ss += v0 * v0 + v1 * v1;
            __nv_bfloat16 h0 = __float2bfloat16(v0), h1 = __float2bfloat16(v1);
            __nv_bfloat16 l0 = __float2bfloat16(v0 - __bfloat162float(h0));
            __nv_bfloat16 l1 = __float2bfloat16(v1 - __bfloat162float(h1));
            int word = lm * RSTR + (pp >> 3) * 8 + pslot(pp & 7);
            Qh[word] = (uint32_t)__bfloat16_as_ushort(h0)
                     | ((uint32_t)__bfloat16_as_ushort(h1) << 16);
            Ql[word] = (uint32_t)__bfloat16_as_ushort(l0)
                     | ((uint32_t)__bfloat16_as_ushort(l1) << 16);
        }
        // ---- stage P: repad 16-word rows -> 24-word rows, uint4 copies ----
        {
            const uint4* srcH = (const uint4*)(g_pbH + (size_t)ch * NP * 16);
            const uint4* srcL = (const uint4*)(g_pbL + (size_t)ch * NP * 16);
#pragma unroll
            for (int i = 0; i < 5; i++) {
                int idx4 = tid + i * 256;        // 0..1279
                int p = idx4 >> 2, q4 = idx4 & 3;
                *(uint4*)&Ph[p * RSTR + q4 * 4] = srcH[idx4];
                *(uint4*)&Pl[p * RSTR + q4 * 4] = srcL[idx4];
            }
        }
        __syncthreads();

#pragma unroll
        for (int s8 = 0; s8 < 2; s8++) {
            uint2 aH0 = *(uint2*)&Qh[(mt + g) * RSTR + s8 * 8 + tig * 2];      // a0,a2
            uint2 aH1 = *(uint2*)&Qh[(mt + g + 8) * RSTR + s8 * 8 + tig * 2];  // a1,a3
            uint2 aL0 = *(uint2*)&Ql[(mt + g) * RSTR + s8 * 8 + tig * 2];
            uint2 aL1 = *(uint2*)&Ql[(mt + g + 8) * RSTR + s8 * 8 + tig * 2];
#pragma unroll
            for (int nt = 0; nt < 20; nt++) {
                int pr = nh * 160 + nt * 8 + g;
                uint2 bH = *(uint2*)&Ph[pr * RSTR + s8 * 8 + tig * 2];  // b0,b1
                uint2 bL = *(uint2*)&Pl[pr * RSTR + s8 * 8 + tig * 2];
                mma16(acc[nt], aH0.x, aH1.x, aH0.y, aH1.y, bH.x, bH.y);  // hh
                mma16(acc[nt], aH0.x, aH1.x, aH0.y, aH1.y, bL.x, bL.y);  // hl
                mma16(acc[nt], aL0.x, aL1.x, aL0.y, aL1.y, bH.x, bH.y);  // lh
            }
        }
        __syncthreads();
    }

    // ---- epilogue scratch aliases into P region (all compute done) ----
    float2* sstat = (float2*)(smw + 3072);   // [64][4]
    float*  sqi   = (float*)(smw + 3584);    // [64]
    float*  sv1   = (float*)(smw + 3648);    // [2][64]
    int*    si1   = (int*)  (smw + 3776);
    float*  sv2   = (float*)(smw + 3904);
    int*    si2   = (int*)  (smw + 4032);
    float*  sse   = (float*)(smw + 4160);
    float*  ssn   = (float*)(smw + 4288);

    sstat[lm * 4 + cq] = make_float2(s, ss);
    __syncthreads();
    if (tid < 64) {
        float S = 0.f, SS = 0.f;
#pragma unroll
        for (int j = 0; j < 4; j++) {
            float2 t = sstat[tid * 4 + j];
            S += t.x; SS += t.y;
        }
        float var = SS - S * S * (1.0f / 256.0f);
        sqi[tid] = TAUF / fmaxf(sqrtf(fmaxf(var, 0.f)), EPSF);
    }
    __syncthreads();

    // per half-pixel-row: lane top-2 -> 4-lane merge -> smem
#pragma unroll
    for (int hv = 0; hv < 2; hv++) {
        int lmx = mt + g + hv * 8;
        float v1 = -1e30f, v2 = -1e30f; int i1 = 0, i2 = 0;
#pragma unroll
        for (int nt = 0; nt < 20; nt++)
#pragma unroll
            for (int cc = 0; cc < 2; cc++) {
                float v = acc[nt][hv * 2 + cc];
                int pidx = nh * 160 + nt * 8 + tig * 2 + cc;
                if (v > v1)      { v2 = v1; i2 = i1; v1 = v; i1 = pidx; }
                else if (v > v2) { v2 = v;  i2 = pidx; }
            }
#pragma unroll
        for (int o = 1; o <= 2; o <<= 1) {
            float Bv1 = __shfl_xor_sync(0xffffffffu, v1, o, 4);
            int   Bi1 = __shfl_xor_sync(0xffffffffu, i1, o, 4);
            float Bv2 = __shfl_xor_sync(0xffffffffu, v2, o, 4);
            int   Bi2 = __shfl_xor_sync(0xffffffffu, i2, o, 4);
            if (Bv1 > v1 || (Bv1 == v1 && Bi1 < i1)) {
                if (v1 > Bv2 || (v1 == Bv2 && i1 < Bi2)) { v2 = v1; i2 = i1; }
                else                                      { v2 = Bv2; i2 = Bi2; }
                v1 = Bv1; i1 = Bi1;
            } else if (Bv1 > v2 || (Bv1 == v2 && Bi1 < i2)) {
                v2 = Bv1; i2 = Bi1;
            }
        }
        if (tig == 0) {
            sv1[nh * 64 + lmx] = v1; si1[nh * 64 + lmx] = i1;
            sv2[nh * 64 + lmx] = v2; si2[nh * 64 + lmx] = i2;
        }
    }
    __syncthreads();

#pragma unroll
    for (int hv = 0; hv < 2; hv++) {
        int lmx = mt + g + hv * 8;
        // merge the two halves' top-2
        float Av1 = sv1[lmx],      Bv1 = sv1[64 + lmx];
        int   Ai1 = si1[lmx],      Bi1 = si1[64 + lmx];
        float Av2 = sv2[lmx],      Bv2 = sv2[64 + lmx];
        int   Ai2 = si2[lmx],      Bi2 = si2[64 + lmx];
        float gv1, gv2; int gi1, gi2;
        if (Bv1 > Av1 || (Bv1 == Av1 && Bi1 < Ai1)) {
            gv1 = Bv1; gi1 = Bi1;
            if (Av1 > Bv2 || (Av1 == Bv2 && Ai1 < Bi2)) { gv2 = Av1; gi2 = Ai1; }
            else                                         { gv2 = Bv2; gi2 = Bi2; }
        } else {
            gv1 = Av1; gi1 = Ai1;
            if (Bv1 > Av2 || (Bv1 == Av2 && Bi1 < Ai2)) { gv2 = Bv1; gi2 = Bi1; }
            else                                         { gv2 = Av2; gi2 = Ai2; }
        }
        (void)gv2;
        float sc = sqi[lmx];
        float se = 0.f, sn = 0.f;
#pragma unroll
        for (int nt = 0; nt < 20; nt++)
#pragma unroll
            for (int cc = 0; cc < 2; cc++) {
                float v = acc[nt][hv * 2 + cc];
                float e = __expf((v - gv1) * sc);
                se += e; sn += e * (v * sc);
            }
#pragma unroll
        for (int o = 1; o <= 2; o <<= 1) {
            se += __shfl_xor_sync(0xffffffffu, se, o, 4);
            sn += __shfl_xor_sync(0xffffffffu, sn, o, 4);
        }
        if (tig == 0) {
            sse[nh * 64 + lmx] = se;
            ssn[nh * 64 + lmx] = sn;
            if (nh == 0) g_top2[m0 + lmx] = make_int2(gi1, gi2);
        }
    }
    __syncthreads();

    if (tid < 64) {
        float SE = sse[tid] + sse[64 + tid];
        float SN = ssn[tid] + ssn[64 + tid];
        out[m0 + tid] = SN / SE;   // pred_grid (noise ~1e-5 rel: fine)
    }
}

// ---------------------------------------------------------------------------
// Kernel E: exact fp32 argmax fixup — recompute the two candidate dists.
// grid 64 x 256 (one thread per pixel).
// ---------------------------------------------------------------------------
__global__ __launch_bounds__(256) void fixup_kernel(const float* __restrict__ qry,
                                                    float* __restrict__ out)
{
    int m = blockIdx.x * 256 + threadIdx.x;
    int2 c2 = g_top2[m];
    const float4* p0 = (const float4*)(g_pn + (size_t)c2.x * NC);
    const float4* p1 = (const float4*)(g_pn + (size_t)c2.y * NC);
    float a0 = 0.f, a1 = 0.f;
#pragma unroll 8
    for (int c4 = 0; c4 < 64; c4++) {
        float4 P0 = p0[c4], P1 = p1[c4];
        float q0 = qry[(size_t)(c4 * 4 + 0) * HW + m];
        float q1 = qry[(size_t)(c4 * 4 + 1) * HW + m];
        float q2 = qry[(size_t)(c4 * 4 + 2) * HW + m];
        float q3 = qry[(size_t)(c4 * 4 + 3) * HW + m];
        a0 = fmaf(q0, P0.x, a0); a0 = fmaf(q1, P0.y, a0);
        a0 = fmaf(q2, P0.z, a0); a0 = fmaf(q3, P0.w, a0);
        a1 = fmaf(q0, P1.x, a1); a1 = fmaf(q1, P1.y, a1);
        a1 = fmaf(q2, P1.z, a1); a1 = fmaf(q3, P1.w, a1);
    }
    int res = (a1 > a0 || (a1 == a0 && c2.y < c2.x)) ? c2.y : c2.x;
    out[HW + m] = (float)res;
}

// ---------------------------------------------------------------------------
#define MAIN_SMEM (18432 * 4)

extern "C" void kernel_launch(void* const* d_in, const int* in_sizes, int n_in,
                              void* d_out, int out_size)
{
    const float* qry = (const float*)d_in[0];   // (1,1,256,128,128)
    const float* sup = (const float*)d_in[1];   // (1,5,1,256,128,128)
    // d_in[2] (sup_y) and d_in[3] (thresh) are dead in the reference.
    float* out = (float*)d_out;                 // [pred_grid | debug_assign]

    cudaFuncSetAttribute(main_kernel, cudaFuncAttributeMaxDynamicSharedMemorySize,
                         MAIN_SMEM);

    pool_kernel<<<dim3(256, 5), 256>>>(sup);
    proto_norm_kernel<<<320, 256>>>();
    main_kernel<<<256, 256, MAIN_SMEM>>>(qry, out);
    fixup_kernel<<<64, 256>>>(qry, out);
}